// round 3
// baseline (speedup 1.0000x reference)
#include <cuda_runtime.h>
#include <cstdint>

#define NA 76725
#define NC 80
#define CA (NA * NC)             // 6,138,000
#define MAXK 200
#define CAND 2048
#define NT 512
#define NWARP (NT / 32)
#define GRID 296
#define N4 ((7 * CA) / 4)        // 10,741,500 float4s in out buffer
#define CH4 4096                 // float4s per fill chunk (64 KB)
#define NCHUNK ((N4 + CH4 - 1) / CH4)
#define FULLMASK 0xFFFFFFFFu
#define NA_PAD (((NA + NT - 1) / NT) * NT)

// -------- device scratch (no allocations allowed) --------
__device__ float g_boxes[NA * 4];
__device__ float g_areas[NA];
__device__ float g_scoresT[(size_t)NC * NA];
__device__ int g_chunk_next;
__device__ int g_chunk_done;

// ============ kernel 1: reset counters + decode + transpose ============
__global__ void k_pre(const float* __restrict__ cls,
                      const float4* __restrict__ reg,
                      const float4* __restrict__ anc) {
    int tid = threadIdx.x;
    if (blockIdx.x == 0 && tid == 0) { g_chunk_next = 0; g_chunk_done = 0; }

    // decode (first 300 blocks' worth of global threads)
    int gid = blockIdx.x * 256 + tid;
    if (gid < NA) {
        float4 a = anc[gid];
        float4 r = reg[gid];
        float aw = a.z - a.x;
        float ah = a.w - a.y;
        float ax = a.x + 0.5f * aw;
        float ay = a.y + 0.5f * ah;
        float cx = ax + r.x * 0.1f * aw;
        float cy = ay + r.y * 0.1f * ah;
        float w = aw * expf(r.z * 0.2f);
        float h = ah * expf(r.w * 0.2f);
        float x1 = fminf(fmaxf(cx - 0.5f * w, 0.0f), 640.0f);
        float y1 = fminf(fmaxf(cy - 0.5f * h, 0.0f), 640.0f);
        float x2 = fminf(fmaxf(cx + 0.5f * w, 0.0f), 640.0f);
        float y2 = fminf(fmaxf(cy + 0.5f * h, 0.0f), 640.0f);
        reinterpret_cast<float4*>(g_boxes)[gid] = make_float4(x1, y1, x2, y2);
        g_areas[gid] = (x2 - x1) * (y2 - y1);
    }

    // transpose [A,80] -> [80,A]
    __shared__ float tile[32 * 81];
    int a0 = blockIdx.x * 32;
    for (int t = tid; t < 32 * 80; t += 256) {
        size_t g = (size_t)a0 * 80 + t;
        if (g < (size_t)NA * 80) {
            int ai = t / 80;
            int c = t - ai * 80;
            tile[ai * 81 + c] = cls[g];
        }
    }
    __syncthreads();
    for (int t = tid; t < 32 * 80; t += 256) {
        int c = t >> 5;
        int ai = t & 31;
        int a = a0 + ai;
        if (a < NA) g_scoresT[(size_t)c * NA + a] = tile[ai * 81 + c];
    }
}

// ============ kernel 2: fill + per-class NMS ============
struct SmemT {
    float4 cbox[CAND];               // 32 KB
    unsigned long long keys[CAND];   // 16 KB
    float  carea[CAND];              // 8 KB
    float4 kbox[MAXK];               // 3.2 KB
    float  karea[MAXK];
    float  kscore[MAXK];
    int    kidx[MAXK];
    int    red[3 * NWARP];
    unsigned mask[32];
    unsigned ph1bits;
    unsigned keepbits;
    int    cnt;
    int    kn;
    int    kn_new;
    int    s_chunk;
};

__device__ __forceinline__ void fill_chunks(float4* __restrict__ out4, SmemT& sm, int tid) {
    const int lo4 = CA / 4, hi4 = (2 * CA) / 4;
    for (;;) {
        if (tid == 0) sm.s_chunk = atomicAdd(&g_chunk_next, 1);
        __syncthreads();
        int c = sm.s_chunk;
        __syncthreads();
        if (c >= NCHUNK) break;
        int base = c * CH4;
#pragma unroll
        for (int it = 0; it < CH4 / NT; it++) {
            int idx = base + it * NT + tid;
            if (idx < N4) {
                float v = (idx >= lo4 && idx < hi4) ? -1.0f : 0.0f;
                out4[idx] = make_float4(v, v, v, v);
            }
        }
        __threadfence();
        __syncthreads();
        if (tid == 0) atomicAdd(&g_chunk_done, 1);
    }
}

__device__ __forceinline__ int count_above(const float* __restrict__ sc, float t,
                                           int tid, int* red) {
    int c = 0;
    for (int j = tid; j < NA; j += NT) c += (__ldg(sc + j) > t) ? 1 : 0;
#pragma unroll
    for (int o = 16; o; o >>= 1) c += __shfl_down_sync(FULLMASK, c, o);
    __syncthreads();                      // protect red from prior use
    if ((tid & 31) == 0) red[tid >> 5] = c;
    __syncthreads();
    if (tid == 0) {
        int s = 0;
        for (int w = 0; w < NWARP; w++) s += red[w];
        red[0] = s;
    }
    __syncthreads();
    int r = red[0];
    __syncthreads();
    return r;
}

__global__ void __launch_bounds__(NT, 2) k_main(float* __restrict__ out) {
    extern __shared__ char raw[];
    SmemT& sm = *reinterpret_cast<SmemT*>(raw);
    const int tid = threadIdx.x;
    const int wid = tid >> 5;
    const int lane = tid & 31;

    if (blockIdx.x >= NC) {               // filler CTA
        fill_chunks(reinterpret_cast<float4*>(out), sm, tid);
        return;
    }
    const int c = blockIdx.x;
    const float* sc = g_scoresT + (size_t)c * NA;

    // ---- ladder count pass: counts above {0.98, 0.90, 0.10}, no atomics ----
    int l0 = 0, l1 = 0, l2 = 0;
    for (int j = tid; j < NA; j += NT) {
        float s = __ldg(sc + j);
        l0 += (s > 0.98f) ? 1 : 0;
        l1 += (s > 0.90f) ? 1 : 0;
        l2 += (s > 0.10f) ? 1 : 0;
    }
#pragma unroll
    for (int o = 16; o; o >>= 1) {
        l0 += __shfl_down_sync(FULLMASK, l0, o);
        l1 += __shfl_down_sync(FULLMASK, l1, o);
        l2 += __shfl_down_sync(FULLMASK, l2, o);
    }
    if (lane == 0) {
        sm.red[wid] = l0;
        sm.red[NWARP + wid] = l1;
        sm.red[2 * NWARP + wid] = l2;
    }
    if (tid == 0) sm.kn = 0;
    __syncthreads();
    if (tid == 0) {
        int a = 0, b = 0, d = 0;
        for (int w = 0; w < NWARP; w++) {
            a += sm.red[w];
            b += sm.red[NWARP + w];
            d += sm.red[2 * NWARP + w];
        }
        sm.red[0] = a; sm.red[1] = b; sm.red[2] = d;
    }
    __syncthreads();
    const int c98 = sm.red[0], c90 = sm.red[1], c10 = sm.red[2];
    __syncthreads();

    // ---- tranche loop ----
    float U = 2.0f;
    int P0 = 0;
    bool exhausted = false;
    for (int tr = 0; tr < 64; tr++) {
        if (sm.kn >= MAXK) break;
        int remaining = c10 - P0;
        if (remaining <= 0) { exhausted = true; break; }

        // choose threshold t so tranche size lands in [320, 1024] (uniform across threads)
        float t = 0.1f;
        int n98 = c98 - P0, n90 = c90 - P0;
        float tLo = 0.f, tHi = 0.f;
        int nLo = 0, nHi = 0;
        bool need = false;
        if (remaining <= 1024) {
            t = 0.1f;
        } else if (n98 >= 320) {
            if (n98 <= 1024) t = 0.98f;
            else { tLo = 0.98f; nLo = n98; tHi = (U > 1.0f ? 1.0f : U); nHi = 0; need = true; }
        } else if (n90 >= 320) {
            if (n90 <= 1024) t = 0.90f;
            else { tLo = 0.90f; nLo = n90; tHi = 0.98f; nHi = (n98 > 0 ? n98 : 0); need = true; }
        } else {
            tLo = 0.10f; nLo = remaining; tHi = 0.90f; nHi = (n90 > 0 ? n90 : 0); need = true;
        }
        if (need) {
            for (int it = 0; it < 8; it++) {
                float frac = (float)(nLo - 640) / (float)(nLo - nHi);
                float tm = tLo + (tHi - tLo) * frac;
                if (!(tm > tLo && tm < tHi)) tm = 0.5f * (tLo + tHi);
                int cm = count_above(sc, tm, tid, sm.red);
                int nm = cm - P0;
                if (nm >= 320 && nm <= 1024) { t = tm; break; }
                if (nm > 1024) { tLo = tm; nLo = nm; }
                else           { tHi = tm; nHi = nm; }
                if (tHi - tLo < 1e-6f || it == 7) { t = tLo; break; }  // accept ≤ CAND side
            }
        }

        // ---- selection (warp-aggregated compaction) ----
        if (tid == 0) sm.cnt = 0;
        __syncthreads();
        for (int j = tid; j < NA_PAD; j += NT) {
            float s = (j < NA) ? __ldg(sc + j) : -1.0f;
            bool p = (s > t) && (s <= U);
            unsigned bal = __ballot_sync(FULLMASK, p);
            if (bal) {
                int base = 0;
                if (lane == 0) base = atomicAdd(&sm.cnt, __popc(bal));
                base = __shfl_sync(FULLMASK, base, 0);
                if (p) {
                    int pos = base + __popc(bal & ((1u << lane) - 1u));
                    if (pos < CAND) {
                        unsigned sb = ~__float_as_uint(s);
                        sm.keys[pos] = ((unsigned long long)sb << 32) | (unsigned)j;
                    }
                }
            }
        }
        __syncthreads();
        int n_tr = sm.cnt;
        if (n_tr > CAND) n_tr = CAND;
        if (n_tr == 0) { P0 = c10; continue; }

        // ---- bitonic sort, adaptive size ----
        int P = 32;
        while (P < n_tr) P <<= 1;
        for (int i = n_tr + tid; i < P; i += NT) sm.keys[i] = ~0ULL;
        __syncthreads();
        for (int k = 2; k <= P; k <<= 1) {
            for (int j2 = k >> 1; j2 > 0; j2 >>= 1) {
                for (int i = tid; i < P; i += NT) {
                    int ixj = i ^ j2;
                    if (ixj > i) {
                        unsigned long long va = sm.keys[i];
                        unsigned long long vb = sm.keys[ixj];
                        bool up = ((i & k) == 0);
                        if ((va > vb) == up) { sm.keys[i] = vb; sm.keys[ixj] = va; }
                    }
                }
                __syncthreads();
            }
        }

        // gather candidate boxes/areas in sorted order
        for (int i = tid; i < n_tr; i += NT) {
            int idx = (int)(unsigned)(sm.keys[i] & 0xFFFFFFFFULL);
            sm.cbox[i] = reinterpret_cast<const float4*>(g_boxes)[idx];
            sm.carea[i] = g_areas[idx];
        }
        __syncthreads();

        // ---- batched speculative greedy (32 candidates/batch, 2 rows/warp) ----
        int pos = 0;
        while (pos < n_tr) {
            int kn0 = sm.kn;
            if (kn0 >= MAXK) break;
            int bn = n_tr - pos;
            if (bn > 32) bn = 32;
            if (tid == 0) sm.ph1bits = 0;
            __syncthreads();

            // phase 1: row r vs confirmed kept list
#pragma unroll
            for (int rr = 0; rr < 2; rr++) {
                int r = wid + rr * 16;
                if (r < bn) {
                    float4 cb = sm.cbox[pos + r];
                    float car = sm.carea[pos + r];
                    bool sup = false;
                    for (int k = lane; k < kn0; k += 32) {
                        float4 kb = sm.kbox[k];
                        float ix1 = fmaxf(cb.x, kb.x);
                        float iy1 = fmaxf(cb.y, kb.y);
                        float ix2 = fminf(cb.z, kb.z);
                        float iy2 = fminf(cb.w, kb.w);
                        float inter = fmaxf(ix2 - ix1, 0.0f) * fmaxf(iy2 - iy1, 0.0f);
                        float iou = inter / (sm.karea[k] + car - inter);
                        if (iou > 0.5f) sup = true;
                    }
                    unsigned b = __ballot_sync(FULLMASK, sup);
                    if (lane == 0 && b) atomicOr(&sm.ph1bits, 1u << r);
                }
            }
            // phase 2: intra-batch pairwise matrix
#pragma unroll
            for (int rr = 0; rr < 2; rr++) {
                int r = wid + rr * 16;
                bool hit = false;
                if (r < bn && lane < bn && lane > r) {
                    float4 wb = sm.cbox[pos + r];
                    float4 jb = sm.cbox[pos + lane];
                    float ix1 = fmaxf(wb.x, jb.x);
                    float iy1 = fmaxf(wb.y, jb.y);
                    float ix2 = fminf(wb.z, jb.z);
                    float iy2 = fminf(wb.w, jb.w);
                    float inter = fmaxf(ix2 - ix1, 0.0f) * fmaxf(iy2 - iy1, 0.0f);
                    float iou = inter / (sm.carea[pos + r] + sm.carea[pos + lane] - inter);
                    hit = iou > 0.5f;
                }
                unsigned m = __ballot_sync(FULLMASK, hit);
                if (lane == 0 && r < bn) sm.mask[r] = m;
            }
            __syncthreads();

            if (tid == 0) {
                unsigned S = sm.ph1bits, keep = 0;
                int knl = kn0;
                for (int i = 0; i < bn; i++) {
                    if (knl >= MAXK) break;
                    if (!((S >> i) & 1u)) {
                        keep |= 1u << i;
                        knl++;
                        S |= sm.mask[i];
                    }
                }
                sm.keepbits = keep;
                sm.kn_new = knl;
            }
            __syncthreads();
            unsigned keep = sm.keepbits;
            if (tid < 32 && ((keep >> tid) & 1u)) {
                int slot = kn0 + __popc(keep & ((1u << tid) - 1u));
                unsigned long long key = sm.keys[pos + tid];
                sm.kbox[slot] = sm.cbox[pos + tid];
                sm.karea[slot] = sm.carea[pos + tid];
                sm.kidx[slot] = (int)(unsigned)(key & 0xFFFFFFFFULL);
                sm.kscore[slot] = __uint_as_float(~(unsigned)(key >> 32));
            }
            __syncthreads();
            if (tid == 0) sm.kn = sm.kn_new;
            __syncthreads();
            pos += 32;
        }

        P0 += n_tr;
        U = t;
    }
    __syncthreads();

    // save kept results to locals before smem reuse by fill_chunks
    int kn = sm.kn;
    // help with fill, then wait for all chunks
    {
        // copy kept data to registers is overkill; fill_chunks only touches s_chunk
        fill_chunks(reinterpret_cast<float4*>(out), sm, tid);
        if (tid == 0) {
            while (atomicAdd(&g_chunk_done, 0) < NCHUNK) __nanosleep(200);
        }
        __syncthreads();
    }

    // ---- scatter kept detections (after defaults are fully written) ----
    // Reference quirk: pool exhausted before MAX_DET iterations forces keep[0]=False.
    for (int i = tid; i < kn; i += NT) {
        int a = sm.kidx[i];
        if (exhausted && a == 0) continue;
        size_t o = (size_t)c * NA + a;
        out[o] = sm.kscore[i];                                              // scores
        out[(size_t)CA + o] = (float)c;                                     // labels
        reinterpret_cast<float4*>(out + 2 * (size_t)CA)[o] = sm.kbox[i];    // boxes
        out[6 * (size_t)CA + o] = 1.0f;                                     // keep
    }
}

// ============ launcher ============
extern "C" void kernel_launch(void* const* d_in, const int* in_sizes, int n_in,
                              void* d_out, int out_size) {
    const float* cls = (const float*)d_in[0];     // [1, A, 80]
    const float4* reg = (const float4*)d_in[1];   // [1, A, 4]
    const float4* anc = (const float4*)d_in[2];   // [A, 4]
    float* out = (float*)d_out;

    cudaFuncSetAttribute(k_main, cudaFuncAttributeMaxDynamicSharedMemorySize,
                         (int)sizeof(SmemT));

    k_pre<<<(NA + 31) / 32, 256>>>(cls, reg, anc);
    k_main<<<GRID, NT, sizeof(SmemT)>>>(out);
}